// round 5
// baseline (speedup 1.0000x reference)
#include <cuda_runtime.h>
#include <math.h>

#define NANCH 896
#define MAXDET 64
#define SLOTS 28          // NANCH / 32
#define WPB 2             // images (warps) per block
#define NT (WPB * 32)

// per-image smem: boxes 896*4 + acc 64*17 + bestv 64  floats
#define IMG_BOX_F   (NANCH * 4)
#define IMG_ACC_F   (MAXDET * 17)
#define IMG_BV_F    (MAXDET)

__global__ __launch_bounds__(NT) void blazeface_warp_kernel(
    const float* __restrict__ raw_boxes,
    const float* __restrict__ raw_scores,
    const float* __restrict__ anchors,
    const float* __restrict__ tmat,
    const int* __restrict__ hp,
    const int* __restrict__ wp,
    float* __restrict__ out,
    int B)
{
    extern __shared__ float sm[];
    const int tid  = threadIdx.x;
    const int lane = tid & 31;
    const int wid  = tid >> 5;
    const int img  = blockIdx.x * WPB + wid;
    if (img >= B) return;

    float* boxes = sm + wid * IMG_BOX_F;                       // [896][4] (y0,x0,y1,x1)
    float* acc   = sm + WPB * IMG_BOX_F + wid * IMG_ACC_F;     // [64][17]
    float* bestv = sm + WPB * (IMG_BOX_F + IMG_ACC_F) + wid * IMG_BV_F;

    const float hf = (float)(*hp);
    const float wf = (float)(*wp);

    const float*  rb  = raw_boxes  + (size_t)img * (NANCH * 16);
    const float4* rb4 = (const float4*)rb;
    const float*  rs  = raw_scores + (size_t)img * NANCH;
    const float4* an4 = (const float4*)anchors;

    // zero the accumulator
    for (int k = lane; k < IMG_ACC_F; k += 32) acc[k] = 0.f;

    // ---- decode: boxes + rem in registers, boxes mirrored to smem ----
    float by0[SLOTS], bx0[SLOTS], by1[SLOTS], bx1[SLOTS], rem[SLOTS];
    unsigned asg[7] = {0u,0u,0u,0u,0u,0u,0u};
    const float inv = 0.0078125f;  // 1/128
    #pragma unroll
    for (int j = 0; j < SLOTS; j++) {
        int a = j * 32 + lane;
        float x = rs[a];
        x = fminf(fmaxf(x, -100.f), 100.f);
        float s = 1.f / (1.f + expf(-x));
        float4 p0 = rb4[a * 4];
        float4 an = an4[a];
        float xc = p0.x * inv * an.z + an.x;
        float yc = p0.y * inv * an.w + an.y;
        float bw = p0.z * inv * an.z;
        float bh = p0.w * inv * an.w;
        float c0 = yc - bh * 0.5f, c1 = xc - bw * 0.5f;
        float c2 = yc + bh * 0.5f, c3 = xc + bw * 0.5f;
        by0[j] = c0; bx0[j] = c1; by1[j] = c2; bx1[j] = c3;
        rem[j] = (s >= 0.5f) ? s : -1.f;
        ((float4*)boxes)[a] = make_float4(c0, c1, c2, c3);
    }
    __syncwarp();

    // ---- phase A: 64 sequential NMS steps (registers + shuffles only) ----
    int nvalid = MAXDET;
    for (int it = 0; it < MAXDET; it++) {
        float bv = -2.f; int bi = 0x7fffffff;
        #pragma unroll
        for (int j = 0; j < SLOTS; j++) {
            if (rem[j] > bv) { bv = rem[j]; bi = j * 32 + lane; }
        }
        #pragma unroll
        for (int o = 16; o > 0; o >>= 1) {
            float ov = __shfl_xor_sync(0xffffffffu, bv, o);
            int   oi = __shfl_xor_sync(0xffffffffu, bi, o);
            if (ov > bv || (ov == bv && oi < bi)) { bv = ov; bi = oi; }
        }
        if (bv <= 0.f) { nvalid = it; break; }
        if (lane == 0) bestv[it] = bv;

        float4 q = ((const float4*)boxes)[bi];   // broadcast LDS, no conflict
        float a1 = fmaxf(q.z - q.x, 0.f) * fmaxf(q.w - q.y, 0.f);

        #pragma unroll
        for (int j = 0; j < SLOTS; j++) {
            if (rem[j] > 0.f) {
                float ymin = fmaxf(q.x, by0[j]), xmin = fmaxf(q.y, bx0[j]);
                float ymax = fminf(q.z, by1[j]), xmax = fminf(q.w, bx1[j]);
                float inter = fmaxf(ymax - ymin, 0.f) * fmaxf(xmax - xmin, 0.f);
                float a2 = fmaxf(by1[j] - by0[j], 0.f) * fmaxf(bx1[j] - bx0[j], 0.f);
                float iou = inter / fmaxf(a1 + a2 - inter, 1e-6f);
                if (iou > 0.3f) {
                    rem[j] = -rem[j];                         // removed: -score
                    asg[j >> 2] |= (unsigned)(it + 1) << ((j & 3) * 8);
                }
            }
        }
    }

    // ---- phase B: parallel deferred blend accumulation ----
    #pragma unroll
    for (int j = 0; j < SLOTS; j++) {
        unsigned v = (asg[j >> 2] >> ((j & 3) * 8)) & 0xffu;
        if (v) {
            int step = (int)v - 1;
            int a = j * 32 + lane;
            float w = -rem[j];                 // recovered score
            float* d = acc + step * 17;
            atomicAdd(d + 0, by0[j] * w);
            atomicAdd(d + 1, bx0[j] * w);
            atomicAdd(d + 2, by1[j] * w);
            atomicAdd(d + 3, bx1[j] * w);
            float4 an = an4[a];
            float4 p1 = rb4[a * 4 + 1];
            float4 p2 = rb4[a * 4 + 2];
            float4 p3 = rb4[a * 4 + 3];
            atomicAdd(d + 4,  (p1.x * inv * an.z + an.x) * w);
            atomicAdd(d + 5,  (p1.y * inv * an.w + an.y) * w);
            atomicAdd(d + 6,  (p1.z * inv * an.z + an.x) * w);
            atomicAdd(d + 7,  (p1.w * inv * an.w + an.y) * w);
            atomicAdd(d + 8,  (p2.x * inv * an.z + an.x) * w);
            atomicAdd(d + 9,  (p2.y * inv * an.w + an.y) * w);
            atomicAdd(d + 10, (p2.z * inv * an.z + an.x) * w);
            atomicAdd(d + 11, (p2.w * inv * an.w + an.y) * w);
            atomicAdd(d + 12, (p3.x * inv * an.z + an.x) * w);
            atomicAdd(d + 13, (p3.y * inv * an.w + an.y) * w);
            atomicAdd(d + 14, (p3.z * inv * an.z + an.x) * w);
            atomicAdd(d + 15, (p3.w * inv * an.w + an.y) * w);
            atomicAdd(d + 16, w);
        }
    }
    __syncwarp();

    // ---- phase C: normalize + project + rescale + write ----
    float mr = (lane < 8) ? tmat[img * 8 + lane] : 0.f;
    float m0 = __shfl_sync(0xffffffffu, mr, 0);
    float m1 = __shfl_sync(0xffffffffu, mr, 1);
    float m3 = __shfl_sync(0xffffffffu, mr, 3);
    float m4 = __shfl_sync(0xffffffffu, mr, 4);
    float m5 = __shfl_sync(0xffffffffu, mr, 5);
    float m7 = __shfl_sync(0xffffffffu, mr, 7);

    float* ob = out + (size_t)img * (MAXDET * 17);
    const int xi[8] = {1,3,4,6,8,10,12,14};
    const int yi[8] = {0,2,5,7,9,11,13,15};
    for (int r = lane; r < MAXDET; r += 32) {
        float* o = ob + r * 17;
        if (r < nvalid) {
            const float* d = acc + r * 17;
            float dn = 1.f / fmaxf(d[16], 1e-6f);
            #pragma unroll
            for (int p = 0; p < 8; p++) {
                float x = d[xi[p]] * dn;
                float y = d[yi[p]] * dn;
                o[xi[p]] = (x * m0 + y * m1 + m3) * wf;
                o[yi[p]] = (x * m4 + y * m5 + m7) * hf;
            }
            o[16] = bestv[r];
        } else {
            #pragma unroll
            for (int k = 0; k < 17; k++) o[k] = 0.f;
        }
    }
}

extern "C" void kernel_launch(void* const* d_in, const int* in_sizes, int n_in,
                              void* d_out, int out_size) {
    const float* raw_boxes  = (const float*)d_in[0];
    const float* raw_scores = (const float*)d_in[1];
    const float* anchors    = (const float*)d_in[2];
    const float* tmat       = (const float*)d_in[3];
    const int*   hp         = (const int*)d_in[4];
    const int*   wp         = (const int*)d_in[5];
    float* out = (float*)d_out;

    int B = in_sizes[1] / NANCH;
    size_t smem = (size_t)WPB * (IMG_BOX_F + IMG_ACC_F + IMG_BV_F) * sizeof(float);
    cudaFuncSetAttribute(blazeface_warp_kernel,
                         cudaFuncAttributeMaxDynamicSharedMemorySize, (int)smem);
    int grid = (B + WPB - 1) / WPB;
    blazeface_warp_kernel<<<grid, NT, smem>>>(raw_boxes, raw_scores, anchors, tmat,
                                              hp, wp, out, B);
}

// round 6
// speedup vs baseline: 2.6098x; 2.6098x over previous
#include <cuda_runtime.h>
#include <math.h>

#define NANCH 896
#define MAXDET 64
#define NT 256
#define SLOTS 4   // ceil(NANCH/NT) compacted slots per thread

__global__ __launch_bounds__(NT, 4) void blazeface_nms_kernel(
    const float* __restrict__ raw_boxes,
    const float* __restrict__ raw_scores,
    const float* __restrict__ anchors,
    const float* __restrict__ tmat,
    const int* __restrict__ hp,
    const int* __restrict__ wp,
    float* __restrict__ out)
{
    __shared__ float4 s_box[NANCH];          // compacted boxes (y0,x0,y1,x1)
    __shared__ float  s_sc[NANCH];           // compacted scores
    __shared__ unsigned short s_aid[NANCH];  // compacted -> anchor id
    __shared__ float  s_acc[MAXDET][17];     // deferred blend accumulator
    __shared__ float  s_bv[MAXDET];          // winning scores
    __shared__ unsigned long long s_key[2];  // double-buffered argmax key
    __shared__ int    s_wcnt[SLOTS][8];
    __shared__ float  s_m[8];

    const int b    = blockIdx.x;
    const int tid  = threadIdx.x;
    const int lane = tid & 31;
    const int wid  = tid >> 5;

    if (tid < 8) s_m[tid] = tmat[b*8 + tid];
    if (tid == 0) { s_key[0] = 0ull; s_key[1] = 0ull; }
    for (int k = tid; k < MAXDET*17; k += NT) ((float*)s_acc)[k] = 0.f;

    const float hf = (float)(*hp);
    const float wf = (float)(*wp);

    const float*  rb  = raw_boxes  + (size_t)b * (NANCH*16);
    const float4* rb4 = (const float4*)rb;
    const float*  rs  = raw_scores + (size_t)b * NANCH;
    const float4* an4 = (const float4*)anchors;
    const float inv = 0.0078125f;  // 1/128

    // ---- phase 1: score + ballots for stable compaction ----
    bool  pred[SLOTS];
    float psc[SLOTS];
    unsigned mk[SLOTS];
    #pragma unroll
    for (int j = 0; j < SLOTS; j++) {
        int a = j*NT + tid;
        pred[j] = false; psc[j] = 0.f;
        if (a < NANCH) {
            float x = rs[a];
            x = fminf(fmaxf(x, -100.f), 100.f);
            float s = 1.f / (1.f + expf(-x));
            psc[j] = s;
            pred[j] = (s >= 0.5f);
        }
        mk[j] = __ballot_sync(0xffffffffu, pred[j]);
        if (lane == 0) s_wcnt[j][wid] = __popc(mk[j]);
    }
    __syncthreads();

    int tot[SLOTS], wbase[SLOTS];
    #pragma unroll
    for (int j = 0; j < SLOTS; j++) {
        int t = 0, wb = 0;
        #pragma unroll
        for (int w = 0; w < 8; w++) {
            int c = s_wcnt[j][w];
            t += c;
            if (w < wid) wb += c;
        }
        tot[j] = t; wbase[j] = wb;
    }
    const int nc = tot[0] + tot[1] + tot[2] + tot[3];

    // ---- phase 2: decode boxes into compacted smem ----
    #pragma unroll
    for (int j = 0; j < SLOTS; j++) {
        if (pred[j]) {
            int off = __popc(mk[j] & ((1u << lane) - 1u)) + wbase[j];
            #pragma unroll
            for (int jp = 0; jp < SLOTS; jp++) if (jp < j) off += tot[jp];
            int a = j*NT + tid;
            float4 p0 = rb4[a*4];
            float4 an = an4[a];
            float xc = p0.x*inv*an.z + an.x;
            float yc = p0.y*inv*an.w + an.y;
            float bw = p0.z*inv*an.z;
            float bh = p0.w*inv*an.w;
            s_box[off] = make_float4(yc - bh*0.5f, xc - bw*0.5f,
                                     yc + bh*0.5f, xc + bw*0.5f);
            s_sc[off]  = psc[j];
            s_aid[off] = (unsigned short)a;
        }
    }
    __syncthreads();

    // ---- phase 3: load owned compacted candidates into registers ----
    float y0[SLOTS], x0[SLOTS], y1[SLOTS], x1[SLOTS], rm[SLOTS];
    int aid[SLOTS];
    unsigned asg = 0u;
    #pragma unroll
    for (int j = 0; j < SLOTS; j++) {
        int c = j*NT + tid;
        rm[j] = -1.f; aid[j] = 0;
        y0[j] = x0[j] = y1[j] = x1[j] = 0.f;
        if (c < nc) {
            float4 q = s_box[c];
            y0[j] = q.x; x0[j] = q.y; y1[j] = q.z; x1[j] = q.w;
            rm[j] = s_sc[c];
            aid[j] = s_aid[c];
        }
    }

    // ---- phase 4: 64 sequential NMS steps ----
    int nvalid = MAXDET;
    for (int it = 0; it < MAXDET; it++) {
        const int p = it & 1;
        // local argmax over slots (slot order = ascending compacted index per thread)
        float bv = 0.f; int bc = 0;
        #pragma unroll
        for (int j = 0; j < SLOTS; j++) {
            if (rm[j] > bv) { bv = rm[j]; bc = j*NT + tid; }
        }
        unsigned long long key = 0ull;
        if (bv > 0.f)
            key = ((unsigned long long)__float_as_uint(bv) << 32)
                | (unsigned long long)(0xffffffffu - (unsigned)bc);
        #pragma unroll
        for (int o = 16; o > 0; o >>= 1) {
            unsigned long long ok = __shfl_xor_sync(0xffffffffu, key, o);
            if (ok > key) key = ok;
        }
        if (lane == 0 && key) atomicMax(&s_key[p], key);
        __syncthreads();

        unsigned long long kk = s_key[p];
        if (kk == 0ull) { nvalid = it; break; }
        float best = __uint_as_float((unsigned)(kk >> 32));
        int   bi   = (int)(0xffffffffu - (unsigned)kk);
        if (tid == 0) { s_bv[it] = best; s_key[p ^ 1] = 0ull; }

        float4 q = s_box[bi];   // broadcast
        float a1 = fmaxf(q.z - q.x, 0.f) * fmaxf(q.w - q.y, 0.f);

        #pragma unroll
        for (int j = 0; j < SLOTS; j++) {
            if (rm[j] > 0.f) {
                float ymin = fmaxf(q.x, y0[j]), xmin = fmaxf(q.y, x0[j]);
                float ymax = fminf(q.z, y1[j]), xmax = fminf(q.w, x1[j]);
                float inter = fmaxf(ymax - ymin, 0.f) * fmaxf(xmax - xmin, 0.f);
                float a2 = fmaxf(y1[j] - y0[j], 0.f) * fmaxf(x1[j] - x0[j], 0.f);
                float iou = inter / fmaxf(a1 + a2 - inter, 1e-6f);
                if (iou > 0.3f) {
                    rm[j] = -rm[j];                       // removed: keep -score
                    asg |= (unsigned)(it + 1) << (j * 8); // record step
                }
            }
        }
        __syncthreads();
    }

    // ---- phase 5: deferred blend accumulation (off critical path) ----
    #pragma unroll
    for (int j = 0; j < SLOTS; j++) {
        unsigned v = (asg >> (j * 8)) & 0xffu;
        if (v) {
            int step = (int)v - 1;
            float w = -rm[j];            // recovered score
            float* d = s_acc[step];
            atomicAdd(d + 0, y0[j] * w);
            atomicAdd(d + 1, x0[j] * w);
            atomicAdd(d + 2, y1[j] * w);
            atomicAdd(d + 3, x1[j] * w);
            int a = aid[j];
            float4 an = an4[a];
            float4 p1 = rb4[a*4 + 1];
            float4 p2 = rb4[a*4 + 2];
            float4 p3 = rb4[a*4 + 3];
            atomicAdd(d + 4,  (p1.x*inv*an.z + an.x) * w);
            atomicAdd(d + 5,  (p1.y*inv*an.w + an.y) * w);
            atomicAdd(d + 6,  (p1.z*inv*an.z + an.x) * w);
            atomicAdd(d + 7,  (p1.w*inv*an.w + an.y) * w);
            atomicAdd(d + 8,  (p2.x*inv*an.z + an.x) * w);
            atomicAdd(d + 9,  (p2.y*inv*an.w + an.y) * w);
            atomicAdd(d + 10, (p2.z*inv*an.z + an.x) * w);
            atomicAdd(d + 11, (p2.w*inv*an.w + an.y) * w);
            atomicAdd(d + 12, (p3.x*inv*an.z + an.x) * w);
            atomicAdd(d + 13, (p3.y*inv*an.w + an.y) * w);
            atomicAdd(d + 14, (p3.z*inv*an.z + an.x) * w);
            atomicAdd(d + 15, (p3.w*inv*an.w + an.y) * w);
            atomicAdd(d + 16, w);
        }
    }
    __syncthreads();

    // ---- phase 6: normalize + project + rescale + write ----
    float* ob = out + (size_t)b * (MAXDET*17);
    const int xi[8] = {1,3,4,6,8,10,12,14};
    const int yi[8] = {0,2,5,7,9,11,13,15};
    if (tid < MAXDET) {
        int r = tid;
        float* o = ob + r*17;
        if (r < nvalid) {
            const float* d = s_acc[r];
            float dn = 1.f / fmaxf(d[16], 1e-6f);
            float m0 = s_m[0], m1 = s_m[1], m3 = s_m[3];
            float m4 = s_m[4], m5 = s_m[5], m7 = s_m[7];
            #pragma unroll
            for (int pidx = 0; pidx < 8; pidx++) {
                float x = d[xi[pidx]] * dn;
                float y = d[yi[pidx]] * dn;
                o[xi[pidx]] = (x*m0 + y*m1 + m3) * wf;
                o[yi[pidx]] = (x*m4 + y*m5 + m7) * hf;
            }
            o[16] = s_bv[r];
        } else {
            #pragma unroll
            for (int k = 0; k < 17; k++) o[k] = 0.f;
        }
    }
}

extern "C" void kernel_launch(void* const* d_in, const int* in_sizes, int n_in,
                              void* d_out, int out_size) {
    const float* raw_boxes  = (const float*)d_in[0];
    const float* raw_scores = (const float*)d_in[1];
    const float* anchors    = (const float*)d_in[2];
    const float* tmat       = (const float*)d_in[3];
    const int*   hp         = (const int*)d_in[4];
    const int*   wp         = (const int*)d_in[5];
    float* out = (float*)d_out;

    int B = in_sizes[1] / NANCH;
    blazeface_nms_kernel<<<B, NT>>>(raw_boxes, raw_scores, anchors, tmat,
                                    hp, wp, out);
}

// round 7
// speedup vs baseline: 3.9857x; 1.5272x over previous
#include <cuda_runtime.h>
#include <math.h>

#define NANCH 896
#define MAXDET 64
#define NT 256
#define SLOTS 4   // ceil(NANCH/NT) compacted slots per thread

__global__ __launch_bounds__(NT, 4) void blazeface_nms_kernel(
    const float* __restrict__ raw_boxes,
    const float* __restrict__ raw_scores,
    const float* __restrict__ anchors,
    const float* __restrict__ tmat,
    const int* __restrict__ hp,
    const int* __restrict__ wp,
    float* __restrict__ out)
{
    __shared__ float4 s_box[NANCH];          // compacted boxes (y0,x0,y1,x1)
    __shared__ float  s_sc[NANCH];           // compacted scores
    __shared__ unsigned short s_aid[NANCH];  // compacted -> anchor id
    __shared__ float  s_acc[MAXDET][17];     // deferred blend accumulator
    __shared__ float  s_bv[MAXDET];          // winning scores
    __shared__ unsigned long long s_key[MAXDET]; // per-step argmax key (no reset)
    __shared__ int    s_wcnt[SLOTS][8];
    __shared__ float  s_m[8];

    const int b    = blockIdx.x;
    const int tid  = threadIdx.x;
    const int lane = tid & 31;
    const int wid  = tid >> 5;

    if (tid < 8) s_m[tid] = tmat[b*8 + tid];
    if (tid < MAXDET) s_key[tid] = 0ull;
    for (int k = tid; k < MAXDET*17; k += NT) ((float*)s_acc)[k] = 0.f;

    const float hf = (float)(*hp);
    const float wf = (float)(*wp);

    const float*  rb  = raw_boxes  + (size_t)b * (NANCH*16);
    const float4* rb4 = (const float4*)rb;
    const float*  rs  = raw_scores + (size_t)b * NANCH;
    const float4* an4 = (const float4*)anchors;
    const float inv = 0.0078125f;  // 1/128

    // ---- phase 1: score + ballots for stable compaction ----
    bool  pred[SLOTS];
    float psc[SLOTS];
    unsigned mk[SLOTS];
    #pragma unroll
    for (int j = 0; j < SLOTS; j++) {
        int a = j*NT + tid;
        pred[j] = false; psc[j] = 0.f;
        if (a < NANCH) {
            float x = rs[a];
            x = fminf(fmaxf(x, -100.f), 100.f);
            float s = 1.f / (1.f + expf(-x));
            psc[j] = s;
            pred[j] = (s >= 0.5f);
        }
        mk[j] = __ballot_sync(0xffffffffu, pred[j]);
        if (lane == 0) s_wcnt[j][wid] = __popc(mk[j]);
    }
    __syncthreads();

    int tot[SLOTS], wbase[SLOTS];
    #pragma unroll
    for (int j = 0; j < SLOTS; j++) {
        int t = 0, wb = 0;
        #pragma unroll
        for (int w = 0; w < 8; w++) {
            int c = s_wcnt[j][w];
            t += c;
            if (w < wid) wb += c;
        }
        tot[j] = t; wbase[j] = wb;
    }
    const int nc = tot[0] + tot[1] + tot[2] + tot[3];

    // ---- phase 2: decode boxes into compacted smem ----
    #pragma unroll
    for (int j = 0; j < SLOTS; j++) {
        if (pred[j]) {
            int off = __popc(mk[j] & ((1u << lane) - 1u)) + wbase[j];
            #pragma unroll
            for (int jp = 0; jp < SLOTS; jp++) if (jp < j) off += tot[jp];
            int a = j*NT + tid;
            float4 p0 = rb4[a*4];
            float4 an = an4[a];
            float xc = p0.x*inv*an.z + an.x;
            float yc = p0.y*inv*an.w + an.y;
            float bw = p0.z*inv*an.z;
            float bh = p0.w*inv*an.w;
            s_box[off] = make_float4(yc - bh*0.5f, xc - bw*0.5f,
                                     yc + bh*0.5f, xc + bw*0.5f);
            s_sc[off]  = psc[j];
            s_aid[off] = (unsigned short)a;
        }
    }
    __syncthreads();

    // ---- phase 3: load owned compacted candidates into registers ----
    float y0[SLOTS], x0[SLOTS], y1[SLOTS], x1[SLOTS], rm[SLOTS], a2[SLOTS];
    int aid[SLOTS];
    unsigned asg = 0u;
    #pragma unroll
    for (int j = 0; j < SLOTS; j++) {
        int c = j*NT + tid;
        rm[j] = -1.f; aid[j] = 0;
        y0[j] = x0[j] = y1[j] = x1[j] = 0.f;
        a2[j] = 0.f;
        if (c < nc) {
            float4 q = s_box[c];
            y0[j] = q.x; x0[j] = q.y; y1[j] = q.z; x1[j] = q.w;
            a2[j] = fmaxf(q.z - q.x, 0.f) * fmaxf(q.w - q.y, 0.f);
            rm[j] = s_sc[c];
            aid[j] = s_aid[c];
        }
    }

    // ---- phase 4: 64 sequential NMS steps (ONE barrier per step) ----
    int nvalid = MAXDET;
    for (int it = 0; it < MAXDET; it++) {
        // local argmax over slots (slot order = ascending compacted index)
        float bv = 0.f; int bc = 0;
        #pragma unroll
        for (int j = 0; j < SLOTS; j++) {
            if (rm[j] > bv) { bv = rm[j]; bc = j*NT + tid; }
        }
        unsigned long long key = 0ull;
        if (bv > 0.f)
            key = ((unsigned long long)__float_as_uint(bv) << 32)
                | (unsigned long long)(0xffffffffu - (unsigned)bc);
        #pragma unroll
        for (int o = 16; o > 0; o >>= 1) {
            unsigned long long ok = __shfl_xor_sync(0xffffffffu, key, o);
            if (ok > key) key = ok;
        }
        if (lane == 0 && key) atomicMax(&s_key[it], key);
        __syncthreads();

        unsigned long long kk = s_key[it];
        if (kk == 0ull) { nvalid = it; break; }
        float best = __uint_as_float((unsigned)(kk >> 32));
        int   bi   = (int)(0xffffffffu - (unsigned)kk);
        if (tid == 0) s_bv[it] = best;

        float4 q = s_box[bi];   // broadcast
        float a1 = fmaxf(q.z - q.x, 0.f) * fmaxf(q.w - q.y, 0.f);

        #pragma unroll
        for (int j = 0; j < SLOTS; j++) {
            if (rm[j] > 0.f) {
                float ymin = fmaxf(q.x, y0[j]), xmin = fmaxf(q.y, x0[j]);
                float ymax = fminf(q.z, y1[j]), xmax = fminf(q.w, x1[j]);
                float inter = fmaxf(ymax - ymin, 0.f) * fmaxf(xmax - xmin, 0.f);
                // iou > 0.3  <=>  inter > 0.3*max(a1+a2-inter, 1e-6)
                if (inter > 0.3f * fmaxf(a1 + a2[j] - inter, 1e-6f)) {
                    rm[j] = -rm[j];                       // removed: keep -score
                    asg |= (unsigned)(it + 1) << (j * 8); // record step
                }
            }
        }
        // no second barrier: next iteration uses a different s_key slot,
        // removals live in registers
    }

    // ---- phase 5: deferred blend accumulation (off critical path) ----
    #pragma unroll
    for (int j = 0; j < SLOTS; j++) {
        unsigned v = (asg >> (j * 8)) & 0xffu;
        if (v) {
            int step = (int)v - 1;
            float w = -rm[j];            // recovered score
            float* d = s_acc[step];
            atomicAdd(d + 0, y0[j] * w);
            atomicAdd(d + 1, x0[j] * w);
            atomicAdd(d + 2, y1[j] * w);
            atomicAdd(d + 3, x1[j] * w);
            int a = aid[j];
            float4 an = an4[a];
            float4 p1 = rb4[a*4 + 1];
            float4 p2 = rb4[a*4 + 2];
            float4 p3 = rb4[a*4 + 3];
            atomicAdd(d + 4,  (p1.x*inv*an.z + an.x) * w);
            atomicAdd(d + 5,  (p1.y*inv*an.w + an.y) * w);
            atomicAdd(d + 6,  (p1.z*inv*an.z + an.x) * w);
            atomicAdd(d + 7,  (p1.w*inv*an.w + an.y) * w);
            atomicAdd(d + 8,  (p2.x*inv*an.z + an.x) * w);
            atomicAdd(d + 9,  (p2.y*inv*an.w + an.y) * w);
            atomicAdd(d + 10, (p2.z*inv*an.z + an.x) * w);
            atomicAdd(d + 11, (p2.w*inv*an.w + an.y) * w);
            atomicAdd(d + 12, (p3.x*inv*an.z + an.x) * w);
            atomicAdd(d + 13, (p3.y*inv*an.w + an.y) * w);
            atomicAdd(d + 14, (p3.z*inv*an.z + an.x) * w);
            atomicAdd(d + 15, (p3.w*inv*an.w + an.y) * w);
            atomicAdd(d + 16, w);
        }
    }
    __syncthreads();

    // ---- phase 6: normalize + project + rescale + write ----
    float* ob = out + (size_t)b * (MAXDET*17);
    const int xi[8] = {1,3,4,6,8,10,12,14};
    const int yi[8] = {0,2,5,7,9,11,13,15};
    if (tid < MAXDET) {
        int r = tid;
        float* o = ob + r*17;
        if (r < nvalid) {
            const float* d = s_acc[r];
            float dn = 1.f / fmaxf(d[16], 1e-6f);
            float m0 = s_m[0], m1 = s_m[1], m3 = s_m[3];
            float m4 = s_m[4], m5 = s_m[5], m7 = s_m[7];
            #pragma unroll
            for (int pidx = 0; pidx < 8; pidx++) {
                float x = d[xi[pidx]] * dn;
                float y = d[yi[pidx]] * dn;
                o[xi[pidx]] = (x*m0 + y*m1 + m3) * wf;
                o[yi[pidx]] = (x*m4 + y*m5 + m7) * hf;
            }
            o[16] = s_bv[r];
        } else {
            #pragma unroll
            for (int k = 0; k < 17; k++) o[k] = 0.f;
        }
    }
}

extern "C" void kernel_launch(void* const* d_in, const int* in_sizes, int n_in,
                              void* d_out, int out_size) {
    const float* raw_boxes  = (const float*)d_in[0];
    const float* raw_scores = (const float*)d_in[1];
    const float* anchors    = (const float*)d_in[2];
    const float* tmat       = (const float*)d_in[3];
    const int*   hp         = (const int*)d_in[4];
    const int*   wp         = (const int*)d_in[5];
    float* out = (float*)d_out;

    int B = in_sizes[1] / NANCH;
    blazeface_nms_kernel<<<B, NT>>>(raw_boxes, raw_scores, anchors, tmat,
                                    hp, wp, out);
}

// round 8
// speedup vs baseline: 4.6782x; 1.1738x over previous
#include <cuda_runtime.h>
#include <math.h>

#define NANCH 896
#define MAXDET 64
#define NT 256
#define SLOTS 4   // ceil(NANCH/NT) compacted slots per thread

__global__ __launch_bounds__(NT, 4) void blazeface_nms_kernel(
    const float* __restrict__ raw_boxes,
    const float* __restrict__ raw_scores,
    const float* __restrict__ anchors,
    const float* __restrict__ tmat,
    const int* __restrict__ hp,
    const int* __restrict__ wp,
    float* __restrict__ out)
{
    __shared__ float4 s_box[NANCH];          // compacted boxes (y0,x0,y1,x1)
    __shared__ float  s_sc[NANCH];           // compacted scores
    __shared__ float  s_area[NANCH];         // compacted box areas
    __shared__ unsigned short s_aid[NANCH];  // compacted -> anchor id
    __shared__ float  s_acc[MAXDET][17];     // deferred blend accumulator
    __shared__ float  s_bv[MAXDET];          // winning scores
    __shared__ unsigned long long s_key[MAXDET]; // per-step argmax key
    __shared__ int    s_wcnt[SLOTS][8];
    __shared__ float  s_m[8];

    const int b    = blockIdx.x;
    const int tid  = threadIdx.x;
    const int lane = tid & 31;
    const int wid  = tid >> 5;

    if (tid < 8) s_m[tid] = tmat[b*8 + tid];
    if (tid < MAXDET) s_key[tid] = 0ull;
    for (int k = tid; k < MAXDET*17; k += NT) ((float*)s_acc)[k] = 0.f;

    const float hf = (float)(*hp);
    const float wf = (float)(*wp);

    const float*  rb  = raw_boxes  + (size_t)b * (NANCH*16);
    const float4* rb4 = (const float4*)rb;
    const float*  rs  = raw_scores + (size_t)b * NANCH;
    const float4* an4 = (const float4*)anchors;
    const float inv = 0.0078125f;  // 1/128

    // ---- phase 1: score + ballots for stable compaction ----
    bool  pred[SLOTS];
    float psc[SLOTS];
    unsigned mk[SLOTS];
    #pragma unroll
    for (int j = 0; j < SLOTS; j++) {
        int a = j*NT + tid;
        pred[j] = false; psc[j] = 0.f;
        if (a < NANCH) {
            float x = rs[a];
            x = fminf(fmaxf(x, -100.f), 100.f);
            float s = 1.f / (1.f + expf(-x));
            psc[j] = s;
            pred[j] = (s >= 0.5f);
        }
        mk[j] = __ballot_sync(0xffffffffu, pred[j]);
        if (lane == 0) s_wcnt[j][wid] = __popc(mk[j]);
    }
    __syncthreads();

    int tot[SLOTS], wbase[SLOTS];
    #pragma unroll
    for (int j = 0; j < SLOTS; j++) {
        int t = 0, wb = 0;
        #pragma unroll
        for (int w = 0; w < 8; w++) {
            int c = s_wcnt[j][w];
            t += c;
            if (w < wid) wb += c;
        }
        tot[j] = t; wbase[j] = wb;
    }
    const int nc = tot[0] + tot[1] + tot[2] + tot[3];

    // ---- phase 2: decode boxes into compacted smem ----
    #pragma unroll
    for (int j = 0; j < SLOTS; j++) {
        if (pred[j]) {
            int off = __popc(mk[j] & ((1u << lane) - 1u)) + wbase[j];
            #pragma unroll
            for (int jp = 0; jp < SLOTS; jp++) if (jp < j) off += tot[jp];
            int a = j*NT + tid;
            float4 p0 = rb4[a*4];
            float4 an = an4[a];
            float xc = p0.x*inv*an.z + an.x;
            float yc = p0.y*inv*an.w + an.y;
            float bw = p0.z*inv*an.z;
            float bh = p0.w*inv*an.w;
            float c0 = yc - bh*0.5f, c1 = xc - bw*0.5f;
            float c2 = yc + bh*0.5f, c3 = xc + bw*0.5f;
            s_box[off]  = make_float4(c0, c1, c2, c3);
            s_area[off] = fmaxf(c2 - c0, 0.f) * fmaxf(c3 - c1, 0.f);
            s_sc[off]   = psc[j];
            s_aid[off]  = (unsigned short)a;
        }
    }
    __syncthreads();

    // ---- phase 3: load owned compacted candidates into registers ----
    float y0[SLOTS], x0[SLOTS], y1[SLOTS], x1[SLOTS], rm[SLOTS], a2[SLOTS];
    int aid[SLOTS];
    unsigned asg = 0u;
    #pragma unroll
    for (int j = 0; j < SLOTS; j++) {
        int c = j*NT + tid;
        rm[j] = -1.f; aid[j] = 0;
        y0[j] = x0[j] = y1[j] = x1[j] = 0.f;
        a2[j] = 0.f;
        if (c < nc) {
            float4 q = s_box[c];
            y0[j] = q.x; x0[j] = q.y; y1[j] = q.z; x1[j] = q.w;
            a2[j] = s_area[c];
            rm[j] = s_sc[c];
            aid[j] = s_aid[c];
        }
    }

    // ---- phase 4: 64 sequential NMS steps (one barrier per step) ----
    int nvalid = MAXDET;
    for (int it = 0; it < MAXDET; it++) {
        // warp argmax via REDUX: max score bits, then min index among holders
        float bv = 0.f;
        #pragma unroll
        for (int j = 0; j < SLOTS; j++) bv = fmaxf(bv, rm[j]);
        unsigned kb = (bv > 0.f) ? __float_as_uint(bv) : 0u;
        unsigned wmax = __reduce_max_sync(0xffffffffu, kb);
        if (wmax != 0u) {
            float mval = __uint_as_float(wmax);
            unsigned ci = 0xffffffffu;
            #pragma unroll
            for (int j = 0; j < SLOTS; j++)
                if (rm[j] == mval) { ci = (unsigned)(j*NT + tid); break; }
            unsigned wmin = __reduce_min_sync(0xffffffffu, ci);
            if (lane == 0) {
                unsigned long long key =
                    ((unsigned long long)wmax << 32)
                  | (unsigned long long)(0xffffffffu - wmin);
                atomicMax(&s_key[it], key);
            }
        }
        __syncthreads();

        unsigned long long kk = s_key[it];
        if (kk == 0ull) { nvalid = it; break; }
        int bi = (int)(0xffffffffu - (unsigned)kk);
        if (tid == 0) s_bv[it] = __uint_as_float((unsigned)(kk >> 32));

        float4 q = s_box[bi];     // broadcast
        float a1 = s_area[bi];    // broadcast

        #pragma unroll
        for (int j = 0; j < SLOTS; j++) {
            if (rm[j] > 0.f) {
                float ymin = fmaxf(q.x, y0[j]), xmin = fmaxf(q.y, x0[j]);
                float ymax = fminf(q.z, y1[j]), xmax = fminf(q.w, x1[j]);
                float inter = fmaxf(ymax - ymin, 0.f) * fmaxf(xmax - xmin, 0.f);
                // iou > 0.3  <=>  inter > 0.3*max(a1+a2-inter, 1e-6)
                if (inter > 0.3f * fmaxf(a1 + a2[j] - inter, 1e-6f)) {
                    rm[j] = -rm[j];                       // removed: keep -score
                    asg |= (unsigned)(it + 1) << (j * 8); // record step
                }
            }
        }
    }

    // ---- phase 5: deferred blend accumulation (off critical path) ----
    #pragma unroll
    for (int j = 0; j < SLOTS; j++) {
        unsigned v = (asg >> (j * 8)) & 0xffu;
        if (v) {
            int step = (int)v - 1;
            float w = -rm[j];            // recovered score
            float* d = s_acc[step];
            atomicAdd(d + 0, y0[j] * w);
            atomicAdd(d + 1, x0[j] * w);
            atomicAdd(d + 2, y1[j] * w);
            atomicAdd(d + 3, x1[j] * w);
            int a = aid[j];
            float4 an = an4[a];
            float4 p1 = rb4[a*4 + 1];
            float4 p2 = rb4[a*4 + 2];
            float4 p3 = rb4[a*4 + 3];
            atomicAdd(d + 4,  (p1.x*inv*an.z + an.x) * w);
            atomicAdd(d + 5,  (p1.y*inv*an.w + an.y) * w);
            atomicAdd(d + 6,  (p1.z*inv*an.z + an.x) * w);
            atomicAdd(d + 7,  (p1.w*inv*an.w + an.y) * w);
            atomicAdd(d + 8,  (p2.x*inv*an.z + an.x) * w);
            atomicAdd(d + 9,  (p2.y*inv*an.w + an.y) * w);
            atomicAdd(d + 10, (p2.z*inv*an.z + an.x) * w);
            atomicAdd(d + 11, (p2.w*inv*an.w + an.y) * w);
            atomicAdd(d + 12, (p3.x*inv*an.z + an.x) * w);
            atomicAdd(d + 13, (p3.y*inv*an.w + an.y) * w);
            atomicAdd(d + 14, (p3.z*inv*an.z + an.x) * w);
            atomicAdd(d + 15, (p3.w*inv*an.w + an.y) * w);
            atomicAdd(d + 16, w);
        }
    }
    __syncthreads();

    // ---- phase 6: normalize + project + rescale + write ----
    float* ob = out + (size_t)b * (MAXDET*17);
    const int xi[8] = {1,3,4,6,8,10,12,14};
    const int yi[8] = {0,2,5,7,9,11,13,15};
    if (tid < MAXDET) {
        int r = tid;
        float* o = ob + r*17;
        if (r < nvalid) {
            const float* d = s_acc[r];
            float dn = 1.f / fmaxf(d[16], 1e-6f);
            float m0 = s_m[0], m1 = s_m[1], m3 = s_m[3];
            float m4 = s_m[4], m5 = s_m[5], m7 = s_m[7];
            #pragma unroll
            for (int pidx = 0; pidx < 8; pidx++) {
                float x = d[xi[pidx]] * dn;
                float y = d[yi[pidx]] * dn;
                o[xi[pidx]] = (x*m0 + y*m1 + m3) * wf;
                o[yi[pidx]] = (x*m4 + y*m5 + m7) * hf;
            }
            o[16] = s_bv[r];
        } else {
            #pragma unroll
            for (int k = 0; k < 17; k++) o[k] = 0.f;
        }
    }
}

extern "C" void kernel_launch(void* const* d_in, const int* in_sizes, int n_in,
                              void* d_out, int out_size) {
    const float* raw_boxes  = (const float*)d_in[0];
    const float* raw_scores = (const float*)d_in[1];
    const float* anchors    = (const float*)d_in[2];
    const float* tmat       = (const float*)d_in[3];
    const int*   hp         = (const int*)d_in[4];
    const int*   wp         = (const int*)d_in[5];
    float* out = (float*)d_out;

    // allow 4 CTAs/SM of ~28.6KB static smem each (default carveout fits only 3)
    cudaFuncSetAttribute(blazeface_nms_kernel,
                         cudaFuncAttributePreferredSharedMemoryCarveout,
                         cudaSharedmemCarveoutMaxShared);

    int B = in_sizes[1] / NANCH;
    blazeface_nms_kernel<<<B, NT>>>(raw_boxes, raw_scores, anchors, tmat,
                                    hp, wp, out);
}

// round 9
// speedup vs baseline: 4.9854x; 1.0657x over previous
#include <cuda_runtime.h>
#include <math.h>

#define NANCH 896
#define MAXDET 64
#define NT 256
#define SLOTS 4   // ceil(NANCH/NT) compacted slots per thread

__global__ __launch_bounds__(NT, 5) void blazeface_nms_kernel(
    const float* __restrict__ raw_boxes,
    const float* __restrict__ raw_scores,
    const float* __restrict__ anchors,
    const float* __restrict__ tmat,
    const int* __restrict__ hp,
    const int* __restrict__ wp,
    float* __restrict__ out)
{
    __shared__ float4 s_box[NANCH];          // compacted boxes (y0,x0,y1,x1)
    __shared__ float  s_sc[NANCH];           // compacted scores
    __shared__ float  s_area[NANCH];         // compacted box areas
    __shared__ unsigned short s_aid[NANCH];  // compacted -> anchor id
    __shared__ float  s_acc[MAXDET][17];     // deferred blend accumulator
    __shared__ float  s_bv[MAXDET];          // winning scores
    __shared__ unsigned long long s_key[MAXDET]; // per-step argmax key
    __shared__ int    s_wcnt[SLOTS][8];
    __shared__ float  s_m[8];

    const int b    = blockIdx.x;
    const int tid  = threadIdx.x;
    const int lane = tid & 31;
    const int wid  = tid >> 5;

    if (tid < 8) s_m[tid] = tmat[b*8 + tid];
    if (tid < MAXDET) s_key[tid] = 0ull;
    for (int k = tid; k < MAXDET*17; k += NT) ((float*)s_acc)[k] = 0.f;

    const float*  rb  = raw_boxes  + (size_t)b * (NANCH*16);
    const float4* rb4 = (const float4*)rb;
    const float*  rs  = raw_scores + (size_t)b * NANCH;
    const float4* an4 = (const float4*)anchors;
    const float inv = 0.0078125f;  // 1/128

    // ---- phase 1: score + ballots for stable compaction ----
    {
        bool  pred[SLOTS];
        float psc[SLOTS];
        unsigned mk[SLOTS];
        #pragma unroll
        for (int j = 0; j < SLOTS; j++) {
            int a = j*NT + tid;
            pred[j] = false; psc[j] = 0.f;
            if (a < NANCH) {
                float x = rs[a];
                x = fminf(fmaxf(x, -100.f), 100.f);
                float s = 1.f / (1.f + expf(-x));
                psc[j] = s;
                pred[j] = (s >= 0.5f);
            }
            mk[j] = __ballot_sync(0xffffffffu, pred[j]);
            if (lane == 0) s_wcnt[j][wid] = __popc(mk[j]);
        }
        __syncthreads();

        int tot[SLOTS], wbase[SLOTS];
        #pragma unroll
        for (int j = 0; j < SLOTS; j++) {
            int t = 0, wb = 0;
            #pragma unroll
            for (int w = 0; w < 8; w++) {
                int c = s_wcnt[j][w];
                t += c;
                if (w < wid) wb += c;
            }
            tot[j] = t; wbase[j] = wb;
        }

        // ---- phase 2: decode boxes into compacted smem ----
        #pragma unroll
        for (int j = 0; j < SLOTS; j++) {
            if (pred[j]) {
                int off = __popc(mk[j] & ((1u << lane) - 1u)) + wbase[j];
                #pragma unroll
                for (int jp = 0; jp < SLOTS; jp++) if (jp < j) off += tot[jp];
                int a = j*NT + tid;
                float4 p0 = rb4[a*4];
                float4 an = an4[a];
                float xc = p0.x*inv*an.z + an.x;
                float yc = p0.y*inv*an.w + an.y;
                float bw = p0.z*inv*an.z;
                float bh = p0.w*inv*an.w;
                float c0 = yc - bh*0.5f, c1 = xc - bw*0.5f;
                float c2 = yc + bh*0.5f, c3 = xc + bw*0.5f;
                s_box[off]  = make_float4(c0, c1, c2, c3);
                s_area[off] = fmaxf(c2 - c0, 0.f) * fmaxf(c3 - c1, 0.f);
                s_sc[off]   = psc[j];
                s_aid[off]  = (unsigned short)a;
            }
        }
        if (tid == 0) s_wcnt[0][0] = tot[0] + tot[1] + tot[2] + tot[3];
    }
    __syncthreads();
    const int nc = s_wcnt[0][0];

    // ---- phase 3: load owned compacted candidates into registers ----
    float y0[SLOTS], x0[SLOTS], y1[SLOTS], x1[SLOTS], rm[SLOTS], a2[SLOTS];
    unsigned asg = 0u;
    #pragma unroll
    for (int j = 0; j < SLOTS; j++) {
        int c = j*NT + tid;
        rm[j] = -1.f;
        y0[j] = x0[j] = y1[j] = x1[j] = 0.f;
        a2[j] = 0.f;
        if (c < nc) {
            float4 q = s_box[c];
            y0[j] = q.x; x0[j] = q.y; y1[j] = q.z; x1[j] = q.w;
            a2[j] = s_area[c];
            rm[j] = s_sc[c];
        }
    }

    // running local max (recomputed only after a removal in this thread)
    float lmax = 0.f;
    #pragma unroll
    for (int j = 0; j < SLOTS; j++) lmax = fmaxf(lmax, rm[j]);

    // ---- phase 4: 64 sequential NMS steps (one barrier per step) ----
    int nvalid = MAXDET;
    for (int it = 0; it < MAXDET; it++) {
        unsigned kb = (lmax > 0.f) ? __float_as_uint(lmax) : 0u;
        unsigned wmax = __reduce_max_sync(0xffffffffu, kb);
        if (wmax != 0u) {
            float mval = __uint_as_float(wmax);
            unsigned ci = 0xffffffffu;
            #pragma unroll
            for (int j = 0; j < SLOTS; j++)
                if (rm[j] == mval) { ci = (unsigned)(j*NT + tid); break; }
            unsigned wmin = __reduce_min_sync(0xffffffffu, ci);
            if (lane == 0) {
                unsigned long long key =
                    ((unsigned long long)wmax << 32)
                  | (unsigned long long)(0xffffffffu - wmin);
                atomicMax(&s_key[it], key);
            }
        }
        __syncthreads();

        unsigned long long kk = s_key[it];
        if (kk == 0ull) { nvalid = it; break; }
        int bi = (int)(0xffffffffu - (unsigned)kk);
        if (tid == 0) s_bv[it] = __uint_as_float((unsigned)(kk >> 32));

        float4 q = s_box[bi];     // broadcast
        float a1 = s_area[bi];    // broadcast

        bool removed = false;
        #pragma unroll
        for (int j = 0; j < SLOTS; j++) {
            if (rm[j] > 0.f) {
                float ymin = fmaxf(q.x, y0[j]), xmin = fmaxf(q.y, x0[j]);
                float ymax = fminf(q.z, y1[j]), xmax = fminf(q.w, x1[j]);
                float inter = fmaxf(ymax - ymin, 0.f) * fmaxf(xmax - xmin, 0.f);
                // iou > 0.3  <=>  inter > 0.3*max(a1+a2-inter, 1e-6)
                if (inter > 0.3f * fmaxf(a1 + a2[j] - inter, 1e-6f)) {
                    rm[j] = -rm[j];                       // removed: keep -score
                    asg |= (unsigned)(it + 1) << (j * 8); // record step
                    removed = true;
                }
            }
        }
        if (removed) {
            lmax = 0.f;
            #pragma unroll
            for (int j = 0; j < SLOTS; j++) lmax = fmaxf(lmax, rm[j]);
        }
    }

    // ---- phase 5: deferred blend accumulation (off critical path) ----
    #pragma unroll
    for (int j = 0; j < SLOTS; j++) {
        unsigned v = (asg >> (j * 8)) & 0xffu;
        if (v) {
            int step = (int)v - 1;
            float w = -rm[j];                    // recovered score
            int a = (int)s_aid[j*NT + tid];      // anchor id from smem
            float* d = s_acc[step];
            atomicAdd(d + 0, y0[j] * w);
            atomicAdd(d + 1, x0[j] * w);
            atomicAdd(d + 2, y1[j] * w);
            atomicAdd(d + 3, x1[j] * w);
            float4 an = an4[a];
            float4 p1 = rb4[a*4 + 1];
            float4 p2 = rb4[a*4 + 2];
            float4 p3 = rb4[a*4 + 3];
            atomicAdd(d + 4,  (p1.x*inv*an.z + an.x) * w);
            atomicAdd(d + 5,  (p1.y*inv*an.w + an.y) * w);
            atomicAdd(d + 6,  (p1.z*inv*an.z + an.x) * w);
            atomicAdd(d + 7,  (p1.w*inv*an.w + an.y) * w);
            atomicAdd(d + 8,  (p2.x*inv*an.z + an.x) * w);
            atomicAdd(d + 9,  (p2.y*inv*an.w + an.y) * w);
            atomicAdd(d + 10, (p2.z*inv*an.z + an.x) * w);
            atomicAdd(d + 11, (p2.w*inv*an.w + an.y) * w);
            atomicAdd(d + 12, (p3.x*inv*an.z + an.x) * w);
            atomicAdd(d + 13, (p3.y*inv*an.w + an.y) * w);
            atomicAdd(d + 14, (p3.z*inv*an.z + an.x) * w);
            atomicAdd(d + 15, (p3.w*inv*an.w + an.y) * w);
            atomicAdd(d + 16, w);
        }
    }
    __syncthreads();

    // ---- phase 6: normalize + project + rescale + write ----
    const float hf = (float)(*hp);
    const float wf = (float)(*wp);
    float* ob = out + (size_t)b * (MAXDET*17);
    const int xi[8] = {1,3,4,6,8,10,12,14};
    const int yi[8] = {0,2,5,7,9,11,13,15};
    if (tid < MAXDET) {
        int r = tid;
        float* o = ob + r*17;
        if (r < nvalid) {
            const float* d = s_acc[r];
            float dn = 1.f / fmaxf(d[16], 1e-6f);
            float m0 = s_m[0], m1 = s_m[1], m3 = s_m[3];
            float m4 = s_m[4], m5 = s_m[5], m7 = s_m[7];
            #pragma unroll
            for (int pidx = 0; pidx < 8; pidx++) {
                float x = d[xi[pidx]] * dn;
                float y = d[yi[pidx]] * dn;
                o[xi[pidx]] = (x*m0 + y*m1 + m3) * wf;
                o[yi[pidx]] = (x*m4 + y*m5 + m7) * hf;
            }
            o[16] = s_bv[r];
        } else {
            #pragma unroll
            for (int k = 0; k < 17; k++) o[k] = 0.f;
        }
    }
}

extern "C" void kernel_launch(void* const* d_in, const int* in_sizes, int n_in,
                              void* d_out, int out_size) {
    const float* raw_boxes  = (const float*)d_in[0];
    const float* raw_scores = (const float*)d_in[1];
    const float* anchors    = (const float*)d_in[2];
    const float* tmat       = (const float*)d_in[3];
    const int*   hp         = (const int*)d_in[4];
    const int*   wp         = (const int*)d_in[5];
    float* out = (float*)d_out;

    cudaFuncSetAttribute(blazeface_nms_kernel,
                         cudaFuncAttributePreferredSharedMemoryCarveout,
                         cudaSharedmemCarveoutMaxShared);

    int B = in_sizes[1] / NANCH;
    blazeface_nms_kernel<<<B, NT>>>(raw_boxes, raw_scores, anchors, tmat,
                                    hp, wp, out);
}

// round 12
// speedup vs baseline: 5.2647x; 1.0560x over previous
#include <cuda_runtime.h>
#include <math.h>

#define NANCH 896
#define MAXDET 64
#define NT 256
#define ACH 4     // anchor chunks (phase 1/2): 4*256 = 896 coverage
#define SLOTS 3   // compacted candidate slots (capacity 768 >> max nc ~500)

__global__ __launch_bounds__(NT, 6) void blazeface_nms_kernel(
    const float* __restrict__ raw_boxes,
    const float* __restrict__ raw_scores,
    const float* __restrict__ anchors,
    const float* __restrict__ tmat,
    const int* __restrict__ hp,
    const int* __restrict__ wp,
    float* __restrict__ out)
{
    __shared__ float4 s_box[NANCH];          // compacted boxes (y0,x0,y1,x1)
    __shared__ float  s_sc[NANCH];           // compacted scores
    __shared__ float  s_area[NANCH];         // compacted box areas
    __shared__ unsigned short s_aid[NANCH];  // compacted -> anchor id
    __shared__ float  s_acc[MAXDET][17];     // deferred blend accumulator
    __shared__ float  s_bv[MAXDET];          // winning scores
    __shared__ unsigned long long s_key[MAXDET]; // per-step argmax key
    __shared__ int    s_wcnt[ACH][8];
    __shared__ float  s_m[8];

    const int b    = blockIdx.x;
    const int tid  = threadIdx.x;
    const int lane = tid & 31;
    const int wid  = tid >> 5;

    if (tid < 8) s_m[tid] = tmat[b*8 + tid];
    if (tid < MAXDET) s_key[tid] = 0ull;
    for (int k = tid; k < MAXDET*17; k += NT) ((float*)s_acc)[k] = 0.f;

    const float*  rb  = raw_boxes  + (size_t)b * (NANCH*16);
    const float4* rb4 = (const float4*)rb;
    const float*  rs  = raw_scores + (size_t)b * NANCH;
    const float4* an4 = (const float4*)anchors;
    const float inv = 0.0078125f;  // 1/128

    // ---- phase 1: score + ballots for stable compaction (anchor space) ----
    {
        bool  pred[ACH];
        float psc[ACH];
        unsigned mk[ACH];
        #pragma unroll
        for (int j = 0; j < ACH; j++) {
            int a = j*NT + tid;
            pred[j] = false; psc[j] = 0.f;
            if (a < NANCH) {
                float x = rs[a];
                x = fminf(fmaxf(x, -100.f), 100.f);
                float s = 1.f / (1.f + expf(-x));
                psc[j] = s;
                pred[j] = (s >= 0.5f);
            }
            mk[j] = __ballot_sync(0xffffffffu, pred[j]);
            if (lane == 0) s_wcnt[j][wid] = __popc(mk[j]);
        }
        __syncthreads();

        int tot[ACH], wbase[ACH];
        #pragma unroll
        for (int j = 0; j < ACH; j++) {
            int t = 0, wb = 0;
            #pragma unroll
            for (int w = 0; w < 8; w++) {
                int c = s_wcnt[j][w];
                t += c;
                if (w < wid) wb += c;
            }
            tot[j] = t; wbase[j] = wb;
        }

        // ---- phase 2: decode boxes into compacted smem ----
        #pragma unroll
        for (int j = 0; j < ACH; j++) {
            if (pred[j]) {
                int off = __popc(mk[j] & ((1u << lane) - 1u)) + wbase[j];
                #pragma unroll
                for (int jp = 0; jp < ACH; jp++) if (jp < j) off += tot[jp];
                int a = j*NT + tid;
                float4 p0 = rb4[a*4];
                float4 an = an4[a];
                float xc = p0.x*inv*an.z + an.x;
                float yc = p0.y*inv*an.w + an.y;
                float bw = p0.z*inv*an.z;
                float bh = p0.w*inv*an.w;
                float c0 = yc - bh*0.5f, c1 = xc - bw*0.5f;
                float c2 = yc + bh*0.5f, c3 = xc + bw*0.5f;
                s_box[off]  = make_float4(c0, c1, c2, c3);
                s_area[off] = fmaxf(c2 - c0, 0.f) * fmaxf(c3 - c1, 0.f);
                s_sc[off]   = psc[j];
                s_aid[off]  = (unsigned short)a;
            }
        }
        if (tid == 0) s_wcnt[0][0] = tot[0] + tot[1] + tot[2] + tot[3];
    }
    __syncthreads();
    const int nc = s_wcnt[0][0];

    // ---- phase 3: load owned compacted candidates into registers ----
    float y0[SLOTS], x0[SLOTS], y1[SLOTS], x1[SLOTS], rm[SLOTS], a2[SLOTS];
    unsigned asg = 0u;
    #pragma unroll
    for (int j = 0; j < SLOTS; j++) {
        int c = j*NT + tid;
        rm[j] = -1.f;
        y0[j] = x0[j] = y1[j] = x1[j] = 0.f;
        a2[j] = 0.f;
        if (c < nc) {
            float4 q = s_box[c];
            y0[j] = q.x; x0[j] = q.y; y1[j] = q.z; x1[j] = q.w;
            a2[j] = s_area[c];
            rm[j] = s_sc[c];
        }
    }

    // running local max (recomputed only after a removal in this thread)
    float lmax = 0.f;
    #pragma unroll
    for (int j = 0; j < SLOTS; j++) lmax = fmaxf(lmax, rm[j]);

    // ---- phase 4: 64 sequential NMS steps (one barrier per step) ----
    int nvalid = MAXDET;
    for (int it = 0; it < MAXDET; it++) {
        unsigned kb = (lmax > 0.f) ? __float_as_uint(lmax) : 0u;
        unsigned wmax = __reduce_max_sync(0xffffffffu, kb);
        if (wmax != 0u) {
            float mval = __uint_as_float(wmax);
            unsigned ci = 0xffffffffu;
            #pragma unroll
            for (int j = 0; j < SLOTS; j++)
                if (rm[j] == mval) { ci = (unsigned)(j*NT + tid); break; }
            unsigned wmin = __reduce_min_sync(0xffffffffu, ci);
            if (lane == 0) {
                unsigned long long key =
                    ((unsigned long long)wmax << 32)
                  | (unsigned long long)(0xffffffffu - wmin);
                atomicMax(&s_key[it], key);
            }
        }
        __syncthreads();

        unsigned long long kk = s_key[it];
        if (kk == 0ull) { nvalid = it; break; }
        int bi = (int)(0xffffffffu - (unsigned)kk);
        if (tid == 0) s_bv[it] = __uint_as_float((unsigned)(kk >> 32));

        float4 q = s_box[bi];     // broadcast
        float a1 = s_area[bi];    // broadcast

        bool removed = false;
        #pragma unroll
        for (int j = 0; j < SLOTS; j++) {
            if (rm[j] > 0.f) {
                float ymin = fmaxf(q.x, y0[j]), xmin = fmaxf(q.y, x0[j]);
                float ymax = fminf(q.z, y1[j]), xmax = fminf(q.w, x1[j]);
                float inter = fmaxf(ymax - ymin, 0.f) * fmaxf(xmax - xmin, 0.f);
                // iou > 0.3  <=>  inter > 0.3*max(a1+a2-inter, 1e-6)   (R7-validated)
                if (inter > 0.3f * fmaxf(a1 + a2[j] - inter, 1e-6f)) {
                    rm[j] = -rm[j];                       // removed: keep -score
                    asg |= (unsigned)(it + 1) << (j * 8); // record step
                    removed = true;
                }
            }
        }
        if (removed) {
            lmax = 0.f;
            #pragma unroll
            for (int j = 0; j < SLOTS; j++) lmax = fmaxf(lmax, rm[j]);
        }
    }

    // ---- phase 5: deferred blend accumulation (off critical path) ----
    #pragma unroll
    for (int j = 0; j < SLOTS; j++) {
        unsigned v = (asg >> (j * 8)) & 0xffu;
        if (v) {
            int step = (int)v - 1;
            float w = -rm[j];                    // recovered score
            int a = (int)s_aid[j*NT + tid];      // anchor id from smem
            float* d = s_acc[step];
            atomicAdd(d + 0, y0[j] * w);
            atomicAdd(d + 1, x0[j] * w);
            atomicAdd(d + 2, y1[j] * w);
            atomicAdd(d + 3, x1[j] * w);
            float4 an = an4[a];
            float4 p1 = rb4[a*4 + 1];
            float4 p2 = rb4[a*4 + 2];
            float4 p3 = rb4[a*4 + 3];
            atomicAdd(d + 4,  (p1.x*inv*an.z + an.x) * w);
            atomicAdd(d + 5,  (p1.y*inv*an.w + an.y) * w);
            atomicAdd(d + 6,  (p1.z*inv*an.z + an.x) * w);
            atomicAdd(d + 7,  (p1.w*inv*an.w + an.y) * w);
            atomicAdd(d + 8,  (p2.x*inv*an.z + an.x) * w);
            atomicAdd(d + 9,  (p2.y*inv*an.w + an.y) * w);
            atomicAdd(d + 10, (p2.z*inv*an.z + an.x) * w);
            atomicAdd(d + 11, (p2.w*inv*an.w + an.y) * w);
            atomicAdd(d + 12, (p3.x*inv*an.z + an.x) * w);
            atomicAdd(d + 13, (p3.y*inv*an.w + an.y) * w);
            atomicAdd(d + 14, (p3.z*inv*an.z + an.x) * w);
            atomicAdd(d + 15, (p3.w*inv*an.w + an.y) * w);
            atomicAdd(d + 16, w);
        }
    }
    __syncthreads();

    // ---- phase 6: normalize + project + rescale + write ----
    const float hf = (float)(*hp);
    const float wf = (float)(*wp);
    float* ob = out + (size_t)b * (MAXDET*17);
    const int xi[8] = {1,3,4,6,8,10,12,14};
    const int yi[8] = {0,2,5,7,9,11,13,15};
    if (tid < MAXDET) {
        int r = tid;
        float* o = ob + r*17;
        if (r < nvalid) {
            const float* d = s_acc[r];
            float dn = 1.f / fmaxf(d[16], 1e-6f);
            float m0 = s_m[0], m1 = s_m[1], m3 = s_m[3];
            float m4 = s_m[4], m5 = s_m[5], m7 = s_m[7];
            #pragma unroll
            for (int pidx = 0; pidx < 8; pidx++) {
                float x = d[xi[pidx]] * dn;
                float y = d[yi[pidx]] * dn;
                o[xi[pidx]] = (x*m0 + y*m1 + m3) * wf;
                o[yi[pidx]] = (x*m4 + y*m5 + m7) * hf;
            }
            o[16] = s_bv[r];
        } else {
            #pragma unroll
            for (int k = 0; k < 17; k++) o[k] = 0.f;
        }
    }
}

extern "C" void kernel_launch(void* const* d_in, const int* in_sizes, int n_in,
                              void* d_out, int out_size) {
    const float* raw_boxes  = (const float*)d_in[0];
    const float* raw_scores = (const float*)d_in[1];
    const float* anchors    = (const float*)d_in[2];
    const float* tmat       = (const float*)d_in[3];
    const int*   hp         = (const int*)d_in[4];
    const int*   wp         = (const int*)d_in[5];
    float* out = (float*)d_out;

    cudaFuncSetAttribute(blazeface_nms_kernel,
                         cudaFuncAttributePreferredSharedMemoryCarveout,
                         cudaSharedmemCarveoutMaxShared);

    int B = in_sizes[1] / NANCH;
    blazeface_nms_kernel<<<B, NT>>>(raw_boxes, raw_scores, anchors, tmat,
                                    hp, wp, out);
}

// round 13
// speedup vs baseline: 6.1258x; 1.1636x over previous
#include <cuda_runtime.h>
#include <math.h>

#define NANCH 896
#define MAXDET 64
#define NT 192
#define NW 6      // warps per block
#define ACH 5     // anchor chunks (phase 1/2): 5*192 = 960 >= 896
#define SLOTS 3   // compacted candidate slots (capacity 576 >> max nc ~500)

__global__ __launch_bounds__(NT, 7) void blazeface_nms_kernel(
    const float* __restrict__ raw_boxes,
    const float* __restrict__ raw_scores,
    const float* __restrict__ anchors,
    const float* __restrict__ tmat,
    const int* __restrict__ hp,
    const int* __restrict__ wp,
    float* __restrict__ out)
{
    __shared__ float4 s_box[NANCH];          // compacted boxes (y0,x0,y1,x1)
    __shared__ float  s_sc[NANCH];           // compacted scores
    __shared__ float  s_area[NANCH];         // compacted box areas
    __shared__ unsigned short s_aid[NANCH];  // compacted -> anchor id
    __shared__ float  s_acc[MAXDET][17];     // deferred blend accumulator
    __shared__ float  s_bv[MAXDET];          // winning scores
    __shared__ unsigned long long s_key[MAXDET]; // per-step argmax key
    __shared__ int    s_wcnt[ACH][NW];
    __shared__ float  s_m[8];

    const int b    = blockIdx.x;
    const int tid  = threadIdx.x;
    const int lane = tid & 31;
    const int wid  = tid >> 5;

    if (tid < 8) s_m[tid] = tmat[b*8 + tid];
    if (tid < MAXDET) s_key[tid] = 0ull;
    for (int k = tid; k < MAXDET*17; k += NT) ((float*)s_acc)[k] = 0.f;

    const float*  rb  = raw_boxes  + (size_t)b * (NANCH*16);
    const float4* rb4 = (const float4*)rb;
    const float*  rs  = raw_scores + (size_t)b * NANCH;
    const float4* an4 = (const float4*)anchors;
    const float inv = 0.0078125f;  // 1/128

    // ---- phase 1: score + ballots for stable compaction (anchor space) ----
    {
        bool  pred[ACH];
        float psc[ACH];
        unsigned mk[ACH];
        #pragma unroll
        for (int j = 0; j < ACH; j++) {
            int a = j*NT + tid;
            pred[j] = false; psc[j] = 0.f;
            if (a < NANCH) {
                float x = rs[a];
                x = fminf(fmaxf(x, -100.f), 100.f);
                float s = 1.f / (1.f + expf(-x));
                psc[j] = s;
                pred[j] = (s >= 0.5f);
            }
            mk[j] = __ballot_sync(0xffffffffu, pred[j]);
            if (lane == 0) s_wcnt[j][wid] = __popc(mk[j]);
        }
        __syncthreads();

        int tot[ACH], wbase[ACH];
        #pragma unroll
        for (int j = 0; j < ACH; j++) {
            int t = 0, wb = 0;
            #pragma unroll
            for (int w = 0; w < NW; w++) {
                int c = s_wcnt[j][w];
                t += c;
                if (w < wid) wb += c;
            }
            tot[j] = t; wbase[j] = wb;
        }

        // ---- phase 2: decode boxes into compacted smem ----
        #pragma unroll
        for (int j = 0; j < ACH; j++) {
            if (pred[j]) {
                int off = __popc(mk[j] & ((1u << lane) - 1u)) + wbase[j];
                #pragma unroll
                for (int jp = 0; jp < ACH; jp++) if (jp < j) off += tot[jp];
                int a = j*NT + tid;
                float4 p0 = rb4[a*4];
                float4 an = an4[a];
                float xc = p0.x*inv*an.z + an.x;
                float yc = p0.y*inv*an.w + an.y;
                float bw = p0.z*inv*an.z;
                float bh = p0.w*inv*an.w;
                float c0 = yc - bh*0.5f, c1 = xc - bw*0.5f;
                float c2 = yc + bh*0.5f, c3 = xc + bw*0.5f;
                s_box[off]  = make_float4(c0, c1, c2, c3);
                s_area[off] = fmaxf(c2 - c0, 0.f) * fmaxf(c3 - c1, 0.f);
                s_sc[off]   = psc[j];
                s_aid[off]  = (unsigned short)a;
            }
        }
        if (tid == 0) {
            int t = 0;
            #pragma unroll
            for (int j = 0; j < ACH; j++) t += tot[j];
            s_wcnt[0][0] = t;
        }
    }
    __syncthreads();
    const int nc = s_wcnt[0][0];

    // ---- phase 3: load owned compacted candidates into registers ----
    float y0[SLOTS], x0[SLOTS], y1[SLOTS], x1[SLOTS], rm[SLOTS], a2[SLOTS];
    unsigned asg = 0u;
    #pragma unroll
    for (int j = 0; j < SLOTS; j++) {
        int c = j*NT + tid;
        rm[j] = -1.f;
        y0[j] = x0[j] = y1[j] = x1[j] = 0.f;
        a2[j] = 0.f;
        if (c < nc) {
            float4 q = s_box[c];
            y0[j] = q.x; x0[j] = q.y; y1[j] = q.z; x1[j] = q.w;
            a2[j] = s_area[c];
            rm[j] = s_sc[c];
        }
    }

    // running local max (recomputed only after a removal in this thread)
    float lmax = 0.f;
    #pragma unroll
    for (int j = 0; j < SLOTS; j++) lmax = fmaxf(lmax, rm[j]);

    // ---- phase 4: 64 sequential NMS steps (one barrier per step) ----
    int nvalid = MAXDET;
    for (int it = 0; it < MAXDET; it++) {
        unsigned kb = (lmax > 0.f) ? __float_as_uint(lmax) : 0u;
        unsigned wmax = __reduce_max_sync(0xffffffffu, kb);
        if (wmax != 0u) {
            float mval = __uint_as_float(wmax);
            unsigned ci = 0xffffffffu;
            #pragma unroll
            for (int j = 0; j < SLOTS; j++)
                if (rm[j] == mval) { ci = (unsigned)(j*NT + tid); break; }
            unsigned wmin = __reduce_min_sync(0xffffffffu, ci);
            if (lane == 0) {
                unsigned long long key =
                    ((unsigned long long)wmax << 32)
                  | (unsigned long long)(0xffffffffu - wmin);
                atomicMax(&s_key[it], key);
            }
        }
        __syncthreads();

        unsigned long long kk = s_key[it];
        if (kk == 0ull) { nvalid = it; break; }
        int bi = (int)(0xffffffffu - (unsigned)kk);
        if (tid == 0) s_bv[it] = __uint_as_float((unsigned)(kk >> 32));

        float4 q = s_box[bi];     // broadcast
        float a1 = s_area[bi];    // broadcast

        bool removed = false;
        #pragma unroll
        for (int j = 0; j < SLOTS; j++) {
            if (rm[j] > 0.f) {
                float ymin = fmaxf(q.x, y0[j]), xmin = fmaxf(q.y, x0[j]);
                float ymax = fminf(q.z, y1[j]), xmax = fminf(q.w, x1[j]);
                float inter = fmaxf(ymax - ymin, 0.f) * fmaxf(xmax - xmin, 0.f);
                // iou > 0.3  <=>  inter > 0.3*max(a1+a2-inter, 1e-6)   (validated)
                if (inter > 0.3f * fmaxf(a1 + a2[j] - inter, 1e-6f)) {
                    rm[j] = -rm[j];                       // removed: keep -score
                    asg |= (unsigned)(it + 1) << (j * 8); // record step
                    removed = true;
                }
            }
        }
        if (removed) {
            lmax = 0.f;
            #pragma unroll
            for (int j = 0; j < SLOTS; j++) lmax = fmaxf(lmax, rm[j]);
        }
    }

    // ---- phase 5: deferred blend accumulation (off critical path) ----
    #pragma unroll
    for (int j = 0; j < SLOTS; j++) {
        unsigned v = (asg >> (j * 8)) & 0xffu;
        if (v) {
            int step = (int)v - 1;
            float w = -rm[j];                    // recovered score
            int a = (int)s_aid[j*NT + tid];      // anchor id from smem
            float* d = s_acc[step];
            atomicAdd(d + 0, y0[j] * w);
            atomicAdd(d + 1, x0[j] * w);
            atomicAdd(d + 2, y1[j] * w);
            atomicAdd(d + 3, x1[j] * w);
            float4 an = an4[a];
            float4 p1 = rb4[a*4 + 1];
            float4 p2 = rb4[a*4 + 2];
            float4 p3 = rb4[a*4 + 3];
            atomicAdd(d + 4,  (p1.x*inv*an.z + an.x) * w);
            atomicAdd(d + 5,  (p1.y*inv*an.w + an.y) * w);
            atomicAdd(d + 6,  (p1.z*inv*an.z + an.x) * w);
            atomicAdd(d + 7,  (p1.w*inv*an.w + an.y) * w);
            atomicAdd(d + 8,  (p2.x*inv*an.z + an.x) * w);
            atomicAdd(d + 9,  (p2.y*inv*an.w + an.y) * w);
            atomicAdd(d + 10, (p2.z*inv*an.z + an.x) * w);
            atomicAdd(d + 11, (p2.w*inv*an.w + an.y) * w);
            atomicAdd(d + 12, (p3.x*inv*an.z + an.x) * w);
            atomicAdd(d + 13, (p3.y*inv*an.w + an.y) * w);
            atomicAdd(d + 14, (p3.z*inv*an.z + an.x) * w);
            atomicAdd(d + 15, (p3.w*inv*an.w + an.y) * w);
            atomicAdd(d + 16, w);
        }
    }
    __syncthreads();

    // ---- phase 6: normalize + project + rescale + write ----
    const float hf = (float)(*hp);
    const float wf = (float)(*wp);
    float* ob = out + (size_t)b * (MAXDET*17);
    const int xi[8] = {1,3,4,6,8,10,12,14};
    const int yi[8] = {0,2,5,7,9,11,13,15};
    if (tid < MAXDET) {
        int r = tid;
        float* o = ob + r*17;
        if (r < nvalid) {
            const float* d = s_acc[r];
            float dn = 1.f / fmaxf(d[16], 1e-6f);
            float m0 = s_m[0], m1 = s_m[1], m3 = s_m[3];
            float m4 = s_m[4], m5 = s_m[5], m7 = s_m[7];
            #pragma unroll
            for (int pidx = 0; pidx < 8; pidx++) {
                float x = d[xi[pidx]] * dn;
                float y = d[yi[pidx]] * dn;
                o[xi[pidx]] = (x*m0 + y*m1 + m3) * wf;
                o[yi[pidx]] = (x*m4 + y*m5 + m7) * hf;
            }
            o[16] = s_bv[r];
        } else {
            #pragma unroll
            for (int k = 0; k < 17; k++) o[k] = 0.f;
        }
    }
}

extern "C" void kernel_launch(void* const* d_in, const int* in_sizes, int n_in,
                              void* d_out, int out_size) {
    const float* raw_boxes  = (const float*)d_in[0];
    const float* raw_scores = (const float*)d_in[1];
    const float* anchors    = (const float*)d_in[2];
    const float* tmat       = (const float*)d_in[3];
    const int*   hp         = (const int*)d_in[4];
    const int*   wp         = (const int*)d_in[5];
    float* out = (float*)d_out;

    cudaFuncSetAttribute(blazeface_nms_kernel,
                         cudaFuncAttributePreferredSharedMemoryCarveout,
                         cudaSharedmemCarveoutMaxShared);

    int B = in_sizes[1] / NANCH;
    blazeface_nms_kernel<<<B, NT>>>(raw_boxes, raw_scores, anchors, tmat,
                                    hp, wp, out);
}